// round 6
// baseline (speedup 1.0000x reference)
#include <cuda_runtime.h>
#include <cuda_bf16.h>
#include <math.h>

#define Bsz 8
#define Lseq 2048
#define Dd 128
#define NROWS (Bsz * Lseq)          // 16384
#define BLD (NROWS * Dd)            // 2097152
#define BDD (Bsz * Dd * Dd)         // 131072
#define NCH 64                      // chunks per sequence
#define CHS 32                      // steps per chunk
#define SPAD 129                    // padded row stride for replay smem

// ---------------- scratch (device globals; no allocation) ----------------
__device__ float g_qkv[NROWS * 512];
__device__ float g_g  [NROWS * 256];
__device__ float g_pk [NROWS * 640];      // q,k,v,alpha,beta per (b,t)
__device__ float g_res[NROWS * Dd];
__device__ float g_out[NROWS * Dd];
__device__ float g_ol [NROWS * Dd];
__device__ float g_snap[Bsz * NCH * Dd * Dd];  // state snapshot at each chunk start

__device__ __forceinline__ float sigf(float x) { return 1.f / (1.f + __expf(-x)); }

// ---------------- generic GEMM: C[n,m] = sum_d A[n,d]*W[m,d] --------------
template <bool SIG>
__global__ void __launch_bounds__(256) gemm_kernel(const float* __restrict__ A, int lda,
                                                   const float* __restrict__ W,
                                                   float* __restrict__ C, int ldc) {
    __shared__ float As[64][17];
    __shared__ float Ws[64][17];
    int bx = blockIdx.x;
    int by = blockIdx.y;
    int tid = threadIdx.x;
    int tx = tid & 15;
    int ty = tid >> 4;
    int lr  = tid >> 2;
    int lk0 = (tid & 3) * 4;

    float acc[4][4];
#pragma unroll
    for (int m = 0; m < 4; m++)
#pragma unroll
        for (int n = 0; n < 4; n++) acc[m][n] = 0.f;

    const float* Arow = A + (size_t)(by * 64 + lr) * lda;
    const float* Wrow = W + (size_t)(bx * 64 + lr) * 128;

#pragma unroll 1
    for (int kt = 0; kt < 8; kt++) {
        int k0 = kt * 16;
        float4 av = *reinterpret_cast<const float4*>(Arow + k0 + lk0);
        float4 wv = *reinterpret_cast<const float4*>(Wrow + k0 + lk0);
        As[lr][lk0 + 0] = av.x; As[lr][lk0 + 1] = av.y;
        As[lr][lk0 + 2] = av.z; As[lr][lk0 + 3] = av.w;
        Ws[lr][lk0 + 0] = wv.x; Ws[lr][lk0 + 1] = wv.y;
        Ws[lr][lk0 + 2] = wv.z; Ws[lr][lk0 + 3] = wv.w;
        __syncthreads();
#pragma unroll
        for (int kk = 0; kk < 16; kk++) {
            float a[4], w[4];
#pragma unroll
            for (int m = 0; m < 4; m++) a[m] = As[ty + 16 * m][kk];
#pragma unroll
            for (int n = 0; n < 4; n++) w[n] = Ws[tx + 16 * n][kk];
#pragma unroll
            for (int m = 0; m < 4; m++)
#pragma unroll
                for (int n = 0; n < 4; n++) acc[m][n] = fmaf(a[m], w[n], acc[m][n]);
        }
        __syncthreads();
    }
#pragma unroll
    for (int m = 0; m < 4; m++) {
        int row = by * 64 + ty + 16 * m;
#pragma unroll
        for (int n = 0; n < 4; n++) {
            int col = bx * 64 + tx + 16 * n;
            float v = acc[m][n];
            if (SIG) v = sigf(v);
            C[(size_t)row * ldc + col] = v;
        }
    }
}

// ------------- depthwise conv(K=3) + sigmoid + L2 norm + pack -------------
__global__ void __launch_bounds__(128) convpack_kernel(const float* __restrict__ qw,
                                                       const float* __restrict__ qb,
                                                       const float* __restrict__ kw,
                                                       const float* __restrict__ kb) {
    int n = blockIdx.x;
    int l = n & (Lseq - 1);
    int d = threadIdx.x;
    int lane = d & 31, w = d >> 5;
    __shared__ float redq[4], redk[4];

    const float* row = g_qkv + (size_t)n * 512;
    float qm = (l > 0)        ? row[-512 + d] : 0.f;
    float qc = row[d];
    float qp = (l < Lseq - 1) ? row[512 + d] : 0.f;
    float yq = fmaf(qw[d * 3 + 0], qm, fmaf(qw[d * 3 + 1], qc, fmaf(qw[d * 3 + 2], qp, qb[d])));
    float sq = sigf(yq);
    float km = (l > 0)        ? row[-512 + 128 + d] : 0.f;
    float kc = row[128 + d];
    float kp = (l < Lseq - 1) ? row[512 + 128 + d] : 0.f;
    float yk = fmaf(kw[d * 3 + 0], km, fmaf(kw[d * 3 + 1], kc, fmaf(kw[d * 3 + 2], kp, kb[d])));
    float sk = sigf(yk);

    float ssq = sq * sq, ssk = sk * sk;
#pragma unroll
    for (int o = 16; o >= 1; o >>= 1) {
        ssq += __shfl_xor_sync(0xffffffffu, ssq, o);
        ssk += __shfl_xor_sync(0xffffffffu, ssk, o);
    }
    if (lane == 0) { redq[w] = ssq; redk[w] = ssk; }
    __syncthreads();
    float nq = sqrtf(redq[0] + redq[1] + redq[2] + redq[3]);
    float nk = sqrtf(redk[0] + redk[1] + redk[2] + redk[3]);
    float qn = sq / fmaxf(nq, 1e-12f);
    float kn = sk / fmaxf(nk, 1e-12f);

    float* out = g_pk + (size_t)n * 640;
    out[d]       = qn;
    out[128 + d] = kn;
    out[256 + d] = row[256 + d];
    out[384 + d] = g_g[(size_t)n * 256 + d];
    out[512 + d] = g_g[(size_t)n * 256 + 128 + d];
}

// ----------------- barrier-free state scan + snapshots --------------------
// 128 CTAs x 256 thr. Warp w owns row i = g*8+w exclusively; lane owns 4 cols.
// NO outputs, NO smem, NO barriers. Dumps state every CHS steps to g_snap.
__global__ void __launch_bounds__(256, 1) scan_kernel(const float* __restrict__ state,
                                                      float* __restrict__ sfin) {
    int b = blockIdx.x >> 4;
    int g = blockIdx.x & 15;
    int tid = threadIdx.x;
    int w = tid >> 5;
    int lane = tid & 31;
    int i = g * 8 + w;
    int j0 = lane * 4;

    float4 s = *reinterpret_cast<const float4*>(state + ((size_t)b * Dd + i) * Dd + j0);

    const float* pkb = g_pk + (size_t)b * Lseq * 640;
    float* snapb = g_snap + (((size_t)b * NCH) * Dd + i) * Dd + j0;   // + c*Dd*Dd

    // prime steps 0 and 1
    float4 kv = *reinterpret_cast<const float4*>(pkb + 128 + j0);
    float4 av = *reinterpret_cast<const float4*>(pkb + 384 + j0);
    float4 bv = *reinterpret_cast<const float4*>(pkb + 512 + j0);
    float vi = pkb[256 + i];
    float4 kv1 = *reinterpret_cast<const float4*>(pkb + 640 + 128 + j0);
    float4 av1 = *reinterpret_cast<const float4*>(pkb + 640 + 384 + j0);
    float4 bv1 = *reinterpret_cast<const float4*>(pkb + 640 + 512 + j0);
    float vi1 = pkb[640 + 256 + i];

#pragma unroll 1
    for (int t0 = 0; t0 < Lseq; t0 += CHS) {
        // snapshot of state ENTERING this chunk
        *reinterpret_cast<float4*>(snapb + (size_t)(t0 >> 5) * Dd * Dd) = s;

#pragma unroll 4
        for (int tt = 0; tt < CHS; tt++) {
            int t = t0 + tt;
            int tn = t + 2 < Lseq ? t + 2 : Lseq - 1;
            const float* pn = pkb + (size_t)tn * 640;
            float4 nk = *reinterpret_cast<const float4*>(pn + 128 + j0);
            float4 na = *reinterpret_cast<const float4*>(pn + 384 + j0);
            float4 nb = *reinterpret_cast<const float4*>(pn + 512 + j0);
            float nv = pn[256 + i];

            float pr = s.x * kv.x;
            pr = fmaf(s.y, kv.y, pr);
            pr = fmaf(s.z, kv.z, pr);
            pr = fmaf(s.w, kv.w, pr);
#pragma unroll
            for (int o = 16; o >= 1; o >>= 1) pr += __shfl_xor_sync(0xffffffffu, pr, o);
            float Sk = pr;

            float bk0 = bv.x * kv.x, bk1 = bv.y * kv.y;
            float bk2 = bv.z * kv.z, bk3 = bv.w * kv.w;
            s.x = fmaf(av.x, s.x, fmaf(vi, bk0, -av.x * bk0 * Sk));
            s.y = fmaf(av.y, s.y, fmaf(vi, bk1, -av.y * bk1 * Sk));
            s.z = fmaf(av.z, s.z, fmaf(vi, bk2, -av.z * bk2 * Sk));
            s.w = fmaf(av.w, s.w, fmaf(vi, bk3, -av.w * bk3 * Sk));

            kv = kv1; av = av1; bv = bv1; vi = vi1;
            kv1 = nk; av1 = na; bv1 = nb; vi1 = nv;
        }
    }

    if (sfin)
        *reinterpret_cast<float4*>(sfin + ((size_t)b * Dd + i) * Dd + j0) = s;
}

// ----------------- parallel output replay per (b,chunk) -------------------
// 512 CTAs x 256 thr, dynamic smem. Loads snapshot, replays 32 steps,
// writes silu(q_t @ S_t) to g_out.
__global__ void __launch_bounds__(256, 1) replay_kernel() {
    extern __shared__ float sm[];
    float* S    = sm;                    // [128][SPAD]
    float* vec0 = S + Dd * SPAD;         // [640]
    float* vec1 = vec0 + 640;            // [640]
    float* Sk   = vec1 + 640;            // [128]
    float* Skp  = Sk + Dd;               // [256]
    float* op   = Skp + 256;             // [256]

    int bc = blockIdx.x;
    int b = bc >> 6, c = bc & 63;
    int tid = threadIdx.x;

    // load snapshot (coalesced)
    const float* snap = g_snap + (size_t)bc * Dd * Dd;
    for (int idx = tid * 4; idx < Dd * Dd; idx += 1024) {
        float4 v = *reinterpret_cast<const float4*>(snap + idx);
        int r = idx >> 7, cc = idx & 127;
        float* d = S + r * SPAD + cc;
        d[0] = v.x; d[1] = v.y; d[2] = v.z; d[3] = v.w;
    }
    const float* pk0 = g_pk + (size_t)(b * Lseq + c * CHS) * 640;
    for (int idx = tid; idx < 640; idx += 256) vec0[idx] = pk0[idx];
    __syncthreads();

    float* outb = g_out + (size_t)(b * Lseq + c * CHS) * Dd;
    float* cur = vec0;
    float* nxt = vec1;

    int r1 = tid & 127, h1 = tid >> 7;       // pass1: row, half
    int j2 = tid & 127, h2 = tid >> 7;       // pass2: col, row-half

#pragma unroll 1
    for (int tt = 0; tt < CHS; tt++) {
        // prefetch next step's vectors
        if (tt < CHS - 1) {
            const float* pn = pk0 + (size_t)(tt + 1) * 640;
            for (int idx = tid; idx < 640; idx += 256) nxt[idx] = pn[idx];
        }

        // pass1: Sk partials (row-major threads)
        {
            const float* kvh = cur + 128 + h1 * 64;
            const float* Srow = S + r1 * SPAD + h1 * 64;
            float a0 = 0.f, a1 = 0.f;
#pragma unroll
            for (int cc = 0; cc < 64; cc += 2) {
                a0 = fmaf(Srow[cc],     kvh[cc],     a0);
                a1 = fmaf(Srow[cc + 1], kvh[cc + 1], a1);
            }
            Skp[h1 * 128 + r1] = a0 + a1;
        }
        __syncthreads();
        if (tid < 128) Sk[tid] = Skp[tid] + Skp[128 + tid];
        __syncthreads();

        // pass2: update column j2 over 64 rows + output partial
        {
            float kj = cur[128 + j2];
            float aj = cur[384 + j2];
            float bj = cur[512 + j2];
            float bkj = bj * kj;
            float ej = aj * bkj;
            float outp = 0.f;
            float* Scol = S + (h2 * 64) * SPAD + j2;
            const float* qv = cur + h2 * 64;
            const float* vv = cur + 256 + h2 * 64;
            const float* skv = Sk + h2 * 64;
#pragma unroll
            for (int rr = 0; rr < 64; rr++) {
                float s = Scol[(size_t)rr * SPAD];
                float snew = fmaf(aj, s, fmaf(bkj, vv[rr], -ej * skv[rr]));
                Scol[(size_t)rr * SPAD] = snew;
                outp = fmaf(qv[rr], snew, outp);
            }
            op[h2 * 128 + j2] = outp;
        }
        __syncthreads();
        if (tid < 128) {
            float o = op[tid] + op[128 + tid];
            outb[(size_t)tt * Dd + tid] = o * sigf(o);
        }

        float* tmp = cur; cur = nxt; nxt = tmp;
    }
}

// --------------------- RMSNorm + scale + residual -------------------------
__global__ void __launch_bounds__(128) rms_kernel(const float* __restrict__ rmsw,
                                                  float* __restrict__ out) {
    int n = blockIdx.x;
    int d = threadIdx.x;
    int lane = d & 31, w = d >> 5;
    __shared__ float red[4];
    float v = g_ol[(size_t)n * Dd + d];
    float ss = v * v;
#pragma unroll
    for (int o = 16; o >= 1; o >>= 1) ss += __shfl_xor_sync(0xffffffffu, ss, o);
    if (lane == 0) red[w] = ss;
    __syncthreads();
    float mean = (red[0] + red[1] + red[2] + red[3]) * (1.f / 128.f);
    float s = rsqrtf(mean + 1e-6f);
    out[(size_t)n * Dd + d] = v * s * rmsw[d] + g_res[(size_t)n * Dd + d];
}

// --------------------------------- launch ---------------------------------
extern "C" void kernel_launch(void* const* d_in, const int* in_sizes, int n_in,
                              void* d_out, int out_size) {
    const float* x      = (const float*)d_in[0];
    const float* state  = (const float*)d_in[1];
    const float* W_in   = (const float*)d_in[2];
    const float* W_gate = (const float*)d_in[3];
    const float* W_out  = (const float*)d_in[4];
    const float* W_res  = (const float*)d_in[5];
    const float* qconvw = (const float*)d_in[6];
    const float* qconvb = (const float*)d_in[7];
    const float* kconvw = (const float*)d_in[8];
    const float* kconvb = (const float*)d_in[9];
    const float* rmsw   = (const float*)d_in[10];
    float* out = (float*)d_out;

    float *qkv, *gg, *res, *outs, *ol;
    cudaGetSymbolAddress((void**)&qkv,  g_qkv);
    cudaGetSymbolAddress((void**)&gg,   g_g);
    cudaGetSymbolAddress((void**)&res,  g_res);
    cudaGetSymbolAddress((void**)&outs, g_out);
    cudaGetSymbolAddress((void**)&ol,   g_ol);

    float* sfin = (out_size >= BLD + BDD) ? (out + BLD) : nullptr;

    static const int replay_smem = (Dd * SPAD + 640 * 2 + Dd + 256 + 256) * 4;
    cudaFuncSetAttribute(replay_kernel, cudaFuncAttributeMaxDynamicSharedMemorySize,
                         replay_smem);

    gemm_kernel<false><<<dim3(512 / 64, NROWS / 64), 256>>>(x, Dd, W_in, qkv, 512);
    gemm_kernel<false><<<dim3(Dd / 64, NROWS / 64), 256>>>(x, Dd, W_res, res, Dd);
    gemm_kernel<true><<<dim3(256 / 64, NROWS / 64), 256>>>(qkv + 384, 512, W_gate, gg, 256);
    convpack_kernel<<<NROWS, 128>>>(qconvw, qconvb, kconvw, kconvb);
    scan_kernel<<<Bsz * 16, 256>>>(state, sfin);
    replay_kernel<<<Bsz * NCH, 256, replay_smem>>>();
    gemm_kernel<false><<<dim3(Dd / 64, NROWS / 64), 256>>>(outs, Dd, W_out, ol, Dd);
    rms_kernel<<<NROWS, 128>>>(rmsw, out);
}